// round 15
// baseline (speedup 1.0000x reference)
#include <cuda_runtime.h>

// Shapes fixed by dataset: b=8, n=1024, m=2048, x_dim=1, c=3, Z=128
#define BB     8
#define NN     1024
#define MM     2048
#define MTB    128         // m-rows per block (128 blocks = single wave on 148 SMs)
#define NCTR   12          // Hermite centers, c_l = l - 5.5, spacing 1
#define KH     10          // Hermite terms k = 0..9  (trunc err ~5e-7)
#define NMOM   (KH*3)      // 30 moments per (batch,center)
#define NBLK   (BB * (MM / MTB))   // 128
#define EPSV   1e-8f
#define LOG2E  1.4426950408889634f
#define K2     (-0.5f * LOG2E)   // exp(-u^2/2) = exp2(K2*u^2)

// Persistent device state. g_bar is epoch-relative (replay-safe).
__device__ unsigned int g_bar;
__device__ float g_moments[BB * NCTR * NMOM];

__device__ __forceinline__ float ex2f(float v) {
    float r;
    asm("ex2.approx.ftz.f32 %0, %1;" : "=f"(r) : "f"(v));
    return r;
}

// ---------------------------------------------------------------------------
// Single fused kernel, 128 blocks x 384 threads, one wave (all blocks resident).
// Fast path:
//   prefetch t-rows + stage W/bias (overlaps phase A)
//   Phase A: blocks 0..95 compute moments for (b,ctr) = blk; 12 warps split n
//   grid barrier (threadfence + epoch counter; deterministic, replay-safe)
//   Phase B: warp = center, 4 rowgroups. Moments read via __ldcg (L2-coherent,
//            NOT __ldg: .nc path is invalid for data written this kernel).
// ---------------------------------------------------------------------------
__global__ __launch_bounds__(384)
void enc_one(const float* __restrict__ x,
             const float* __restrict__ y,
             const float* __restrict__ t,
             const float* __restrict__ sigma,
             const float* __restrict__ W,
             const float* __restrict__ bfc,
             float* __restrict__ out)
{
    __shared__ float  part[NCTR][NMOM];  // phase-A per-warp partials (1.4 KB)
    __shared__ float4 red[NCTR][MTB];    // 24 KB per-center row partials
    __shared__ float4 zfin[MTB];         //  2 KB
    __shared__ float4 sW[96];            //  1.5 KB
    __shared__ float4 sB[32];            //  0.5 KB

    const int tid  = threadIdx.x;
    const int lane = tid & 31;
    const int wrp  = tid >> 5;          // 0..11
    const int blk  = blockIdx.x;
    const int b    = blk >> 4;          // 16 m-tiles per batch
    const int m_base = (blk & 15) * MTB;

    const float C0 = -0.5f * LOG2E * __expf(-2.f * sigma[0]);
    const float C1 = -0.5f * LOG2E * __expf(-2.f * sigma[1]);
    const float C2 = -0.5f * LOG2E * __expf(-2.f * sigma[2]);
    const float s  = __expf(sigma[0]);
    const bool fast = (C0 == C1) && (C0 == C2) && (s >= 0.8f) && (s <= 1.25f);

    // Prefetch this thread's 4 t-rows early (MLP=4; overlaps phase A latency)
    float tmv[4];
    #pragma unroll
    for (int rg = 0; rg < 4; ++rg)
        tmv[rg] = __ldg(t + b * MM + m_base + rg * 32 + lane);

    // Stage W + bias
    if (tid < 96) sW[tid] = reinterpret_cast<const float4*>(W)[tid];
    else if (tid < 128) sB[tid - 96] = reinterpret_cast<const float4*>(bfc)[tid - 96];

    if (fast) {
        const float s_inv = 1.f / s;

        // ---- Phase A: blocks 0..95 compute moments for pair (mb, mc) = blk ----
        if (blk < BB * NCTR) {
            const int mb = blk / NCTR;
            const int mc = blk % NCTR;
            const float c = (float)mc - 5.5f;
            const float INVK[KH] = {0.f, 1.f, 0.5f, 1.f/3.f, 0.25f, 0.2f,
                                    1.f/6.f, 1.f/7.f, 0.125f, 1.f/9.f};

            float a0[KH], a1[KH], a2[KH];
            #pragma unroll
            for (int k = 0; k < KH; ++k) { a0[k] = 0.f; a1[k] = 0.f; a2[k] = 0.f; }

            const float*  xb = x + mb * NN;
            const float2* yb = reinterpret_cast<const float2*>(y + mb * NN * 2);

            const int jlo = (NN * wrp) / NCTR;
            const int jhi = (NN * (wrp + 1)) / NCTR;
            for (int j = jlo + lane; j < jhi; j += 32) {
                float xv = __ldg(xb + j) * s_inv;
                int l = (int)floorf(xv + 6.0f);
                l = min(max(l, 0), NCTR - 1);
                if (l == mc) {
                    float2 yv = __ldg(yb + j);
                    float w = xv - c;
                    float p = 1.f;
                    a0[0] += 1.f; a1[0] += yv.x; a2[0] += yv.y;
                    #pragma unroll
                    for (int k = 1; k < KH; ++k) {
                        p = p * w * INVK[k];
                        a0[k] += p;
                        a1[k] = fmaf(p, yv.x, a1[k]);
                        a2[k] = fmaf(p, yv.y, a2[k]);
                    }
                }
            }

            // Warp butterfly (30 accumulators)
            #pragma unroll
            for (int off = 16; off; off >>= 1) {
                #pragma unroll
                for (int k = 0; k < KH; ++k) {
                    a0[k] += __shfl_xor_sync(0xffffffffu, a0[k], off);
                    a1[k] += __shfl_xor_sync(0xffffffffu, a1[k], off);
                    a2[k] += __shfl_xor_sync(0xffffffffu, a2[k], off);
                }
            }
            if (lane == 0) {
                #pragma unroll
                for (int k = 0; k < KH; ++k) {
                    part[wrp][k * 3 + 0] = a0[k];
                    part[wrp][k * 3 + 1] = a1[k];
                    part[wrp][k * 3 + 2] = a2[k];
                }
            }
            __syncthreads();

            if (tid < NMOM) {
                float acc = 0.f;
                #pragma unroll
                for (int wdx = 0; wdx < NCTR; ++wdx) acc += part[wdx][tid];
                g_moments[(mb * NCTR + mc) * NMOM + tid] = acc;
            }
        }

        // ---- Grid barrier (epoch-relative; deterministic across graph replays) ----
        __syncthreads();
        if (tid == 0) {
            __threadfence();                                   // publish g_moments
            unsigned my = atomicAdd(&g_bar, 1u) + 1u;          // arrival number
            unsigned target = ((my + (NBLK - 1u)) / NBLK) * NBLK;
            while (*(volatile unsigned int*)&g_bar < target) { }
            __threadfence();
        }
        __syncthreads();

        // ---- Phase B: warp = center, 4 rowgroups of 32 rows ----
        {
            const float c = (float)wrp - 5.5f;
            const float* Mc = g_moments + (b * NCTR + wrp) * NMOM;
            float M[NMOM];
            #pragma unroll
            for (int i = 0; i < NMOM; ++i) M[i] = __ldcg(Mc + i);  // L2 load (coherent)

            #pragma unroll
            for (int rg = 0; rg < 4; ++rg) {
                const int row = rg * 32 + lane;
                const float u = tmv[rg] * s_inv - c;
                const float E = ex2f(K2 * u * u);

                float Hk2 = E;                    // He_0 * E
                float s0 = M[0] * Hk2;
                float s1 = M[1] * Hk2;
                float s2 = M[2] * Hk2;
                float Hk1 = u * E;                // He_1 * E
                s0 = fmaf(M[3], Hk1, s0);
                s1 = fmaf(M[4], Hk1, s1);
                s2 = fmaf(M[5], Hk1, s2);
                #pragma unroll
                for (int k = 2; k < KH; ++k) {
                    float Hk = fmaf(u, Hk1, -(float)(k - 1) * Hk2);  // He recurrence * E
                    s0 = fmaf(M[k * 3 + 0], Hk, s0);
                    s1 = fmaf(M[k * 3 + 1], Hk, s1);
                    s2 = fmaf(M[k * 3 + 2], Hk, s2);
                    Hk2 = Hk1; Hk1 = Hk;
                }
                red[wrp][row] = make_float4(s0, s1, s2, 0.f);
            }
        }
    } else {
        // Exact direct fallback: warp wrp scans its n-slice for all 128 rows
        const int nstart = wrp * 86;
        const int nend   = min(NN, nstart + 86);
        const float*  xb = x + b * NN;
        const float2* yb = reinterpret_cast<const float2*>(y + b * NN * 2);
        #pragma unroll
        for (int rg = 0; rg < 4; ++rg) {
            const int row = rg * 32 + lane;
            const float tr = tmv[rg];
            float s0 = 0.f, s1 = 0.f, s2 = 0.f;
            for (int i = nstart; i < nend; ++i) {
                float  d  = tr - __ldg(xb + i);
                float2 yv = __ldg(yb + i);
                float d2 = d * d;
                float e0 = ex2f(C0 * d2);
                float e1 = ex2f(C1 * d2);
                float e2 = ex2f(C2 * d2);
                s0 += e0;
                s1 = fmaf(e1, yv.x, s1);
                s2 = fmaf(e2, yv.y, s2);
            }
            red[wrp][row] = make_float4(s0, s1, s2, 0.f);
        }
    }
    __syncthreads();

    // Combine 12 center/slice partials per row, normalize (128 threads)
    if (tid < MTB) {
        float d0 = 0.f, d1 = 0.f, d2 = 0.f;
        #pragma unroll
        for (int wdx = 0; wdx < NCTR; ++wdx) {
            float4 p = red[wdx][tid];
            d0 += p.x; d1 += p.y; d2 += p.z;
        }
        float inv = 1.f / (d0 + EPSV);
        zfin[tid] = make_float4(d0, d1 * inv, d2 * inv, 0.f);
    }
    __syncthreads();

    // Epilogue: 128 rows x 32 col-groups = 4096 float4 stores over 384 threads
    float4* out4 = reinterpret_cast<float4*>(out);
    const size_t rowbase = (size_t)(b * MM + m_base);
    for (int j = tid; j < MTB * 32; j += 384) {
        const int row = j >> 5;
        const int k4  = j & 31;
        const float4 z  = zfin[row];
        const float4 wa = sW[3 * k4];
        const float4 wb = sW[3 * k4 + 1];
        const float4 wc = sW[3 * k4 + 2];
        const float4 bb = sB[k4];
        float4 o;
        o.x = fmaf(z.x, wa.x, fmaf(z.y, wa.y, fmaf(z.z, wa.z, bb.x)));
        o.y = fmaf(z.x, wa.w, fmaf(z.y, wb.x, fmaf(z.z, wb.y, bb.y)));
        o.z = fmaf(z.x, wb.z, fmaf(z.y, wb.w, fmaf(z.z, wc.x, bb.z)));
        o.w = fmaf(z.x, wc.y, fmaf(z.y, wc.z, fmaf(z.z, wc.w, bb.w)));
        out4[(rowbase + row) * 32 + k4] = o;
    }
}

extern "C" void kernel_launch(void* const* d_in, const int* in_sizes, int n_in,
                              void* d_out, int out_size)
{
    const float* x     = (const float*)d_in[0];   // (8,1024,1)
    const float* y     = (const float*)d_in[1];   // (8,1024,2)
    const float* t     = (const float*)d_in[2];   // (8,2048,1)
    const float* sigma = (const float*)d_in[3];   // (3,)
    const float* W     = (const float*)d_in[4];   // (128,3)
    const float* bfc   = (const float*)d_in[5];   // (128,)
    float* out = (float*)d_out;                   // (8,2048,128)

    enc_one<<<NBLK, 384>>>(x, y, t, sigma, W, bfc, out);
}

// round 16
// speedup vs baseline: 1.0201x; 1.0201x over previous
#include <cuda_runtime.h>

// Shapes fixed by dataset: b=8, n=1024, m=2048, x_dim=1, c=3, Z=128
#define BB     8
#define NN     1024
#define MM     2048
#define MTB    128         // m-rows per block (128 blocks = single wave on 148 SMs)
#define NCTR   12          // Hermite centers, c_l = l - 5.5, spacing 1
#define KH     10          // Hermite terms k = 0..9  (trunc err ~5e-7)
#define NMOM   (KH*3)      // 30 moments per (batch,center)
#define NBLK   (BB * (MM / MTB))   // 128
#define EPSV   1e-8f
#define LOG2E  1.4426950408889634f
#define K2     (-0.5f * LOG2E)   // exp(-u^2/2) = exp2(K2*u^2)

// Persistent device state (epoch-relative counters: replay-safe, deterministic).
// Padded to one 128B line per batch to avoid cross-batch contention.
__device__ unsigned int g_arr[BB * 32];
__device__ unsigned int g_done[BB * 32];
__device__ float g_moments[BB * NCTR * NMOM];

__device__ __forceinline__ float ex2f(float v) {
    float r;
    asm("ex2.approx.ftz.f32 %0, %1;" : "=f"(r) : "f"(v));
    return r;
}

// ---------------------------------------------------------------------------
// Single fused kernel, 128 blocks x 384 threads, one wave (all blocks resident).
// Per-batch synchronization: block 16b+c (c<12) produces moments (b,c); the
// 16 blocks of batch b wait only on their own 12 producers (launch-adjacent).
// ---------------------------------------------------------------------------
__global__ __launch_bounds__(384)
void enc_one(const float* __restrict__ x,
             const float* __restrict__ y,
             const float* __restrict__ t,
             const float* __restrict__ sigma,
             const float* __restrict__ W,
             const float* __restrict__ bfc,
             float* __restrict__ out)
{
    __shared__ float  part[NCTR][NMOM];  // phase-A per-warp partials (1.4 KB)
    __shared__ float4 red[NCTR][MTB];    // 24 KB per-center row partials
    __shared__ float4 zfin[MTB];         //  2 KB
    __shared__ float4 sW[96];            //  1.5 KB
    __shared__ float4 sB[32];            //  0.5 KB

    const int tid  = threadIdx.x;
    const int lane = tid & 31;
    const int wrp  = tid >> 5;          // 0..11
    const int blk  = blockIdx.x;
    const int b    = blk >> 4;          // 16 blocks per batch
    const int sub  = blk & 15;          // 0..15 within batch (0..11 = producers)
    const int m_base = sub * MTB;

    const float C0 = -0.5f * LOG2E * __expf(-2.f * sigma[0]);
    const float C1 = -0.5f * LOG2E * __expf(-2.f * sigma[1]);
    const float C2 = -0.5f * LOG2E * __expf(-2.f * sigma[2]);
    const float s  = __expf(sigma[0]);
    const bool fast = (C0 == C1) && (C0 == C2) && (s >= 0.8f) && (s <= 1.25f);

    // Prefetch this thread's 4 t-rows early (MLP=4; overlaps phase A latency)
    float tmv[4];
    #pragma unroll
    for (int rg = 0; rg < 4; ++rg)
        tmv[rg] = __ldg(t + b * MM + m_base + rg * 32 + lane);

    // Stage W + bias
    if (tid < 96) sW[tid] = reinterpret_cast<const float4*>(W)[tid];
    else if (tid < 128) sB[tid - 96] = reinterpret_cast<const float4*>(bfc)[tid - 96];

    if (fast) {
        const float s_inv = 1.f / s;

        // ---- Phase A: block 16b+c (c<12) computes moments for (b, c) ----
        if (sub < NCTR) {
            const int mc = sub;
            const float c = (float)mc - 5.5f;
            const float INVK[KH] = {0.f, 1.f, 0.5f, 1.f/3.f, 0.25f, 0.2f,
                                    1.f/6.f, 1.f/7.f, 0.125f, 1.f/9.f};

            float a0[KH], a1[KH], a2[KH];
            #pragma unroll
            for (int k = 0; k < KH; ++k) { a0[k] = 0.f; a1[k] = 0.f; a2[k] = 0.f; }

            const float*  xb = x + b * NN;
            const float2* yb = reinterpret_cast<const float2*>(y + b * NN * 2);

            const int jlo = (NN * wrp) / NCTR;
            const int jhi = (NN * (wrp + 1)) / NCTR;
            for (int j = jlo + lane; j < jhi; j += 32) {
                float xv = __ldg(xb + j) * s_inv;
                int l = (int)floorf(xv + 6.0f);
                l = min(max(l, 0), NCTR - 1);
                if (l == mc) {
                    float2 yv = __ldg(yb + j);
                    float w = xv - c;
                    float p = 1.f;
                    a0[0] += 1.f; a1[0] += yv.x; a2[0] += yv.y;
                    #pragma unroll
                    for (int k = 1; k < KH; ++k) {
                        p = p * w * INVK[k];
                        a0[k] += p;
                        a1[k] = fmaf(p, yv.x, a1[k]);
                        a2[k] = fmaf(p, yv.y, a2[k]);
                    }
                }
            }

            // Warp butterfly (30 accumulators)
            #pragma unroll
            for (int off = 16; off; off >>= 1) {
                #pragma unroll
                for (int k = 0; k < KH; ++k) {
                    a0[k] += __shfl_xor_sync(0xffffffffu, a0[k], off);
                    a1[k] += __shfl_xor_sync(0xffffffffu, a1[k], off);
                    a2[k] += __shfl_xor_sync(0xffffffffu, a2[k], off);
                }
            }
            if (lane == 0) {
                #pragma unroll
                for (int k = 0; k < KH; ++k) {
                    part[wrp][k * 3 + 0] = a0[k];
                    part[wrp][k * 3 + 1] = a1[k];
                    part[wrp][k * 3 + 2] = a2[k];
                }
            }
            __syncthreads();

            if (tid < NMOM) {
                float acc = 0.f;
                #pragma unroll
                for (int wdx = 0; wdx < NCTR; ++wdx) acc += part[wdx][tid];
                g_moments[(b * NCTR + mc) * NMOM + tid] = acc;
            }
        }

        // ---- Per-batch barrier (epoch-relative; deterministic, replay-safe) ----
        __syncthreads();
        if (tid == 0) {
            if (sub < NCTR) {
                __threadfence();                       // publish this block's moments
                atomicAdd(&g_done[b * 32], 1u);
            }
            unsigned my = atomicAdd(&g_arr[b * 32], 1u) + 1u;   // arrival in batch b
            unsigned epoch = (my + 15u) / 16u;
            unsigned target = epoch * NCTR;            // 12 producers per epoch
            while (*(volatile unsigned int*)&g_done[b * 32] < target) { }
            __threadfence();
        }
        __syncthreads();

        // ---- Phase B: warp = center, 4 rowgroups of 32 rows ----
        {
            const float c = (float)wrp - 5.5f;
            const float* Mc = g_moments + (b * NCTR + wrp) * NMOM;
            float M[NMOM];
            #pragma unroll
            for (int i = 0; i < NMOM; ++i) M[i] = __ldcg(Mc + i);  // L2 (coherent)

            #pragma unroll
            for (int rg = 0; rg < 4; ++rg) {
                const int row = rg * 32 + lane;
                const float u = tmv[rg] * s_inv - c;
                const float E = ex2f(K2 * u * u);

                float Hk2 = E;                    // He_0 * E
                float s0 = M[0] * Hk2;
                float s1 = M[1] * Hk2;
                float s2 = M[2] * Hk2;
                float Hk1 = u * E;                // He_1 * E
                s0 = fmaf(M[3], Hk1, s0);
                s1 = fmaf(M[4], Hk1, s1);
                s2 = fmaf(M[5], Hk1, s2);
                #pragma unroll
                for (int k = 2; k < KH; ++k) {
                    float Hk = fmaf(u, Hk1, -(float)(k - 1) * Hk2);  // He recurrence * E
                    s0 = fmaf(M[k * 3 + 0], Hk, s0);
                    s1 = fmaf(M[k * 3 + 1], Hk, s1);
                    s2 = fmaf(M[k * 3 + 2], Hk, s2);
                    Hk2 = Hk1; Hk1 = Hk;
                }
                red[wrp][row] = make_float4(s0, s1, s2, 0.f);
            }
        }
    } else {
        // Exact direct fallback: warp wrp scans its n-slice for all 128 rows
        const int nstart = wrp * 86;
        const int nend   = min(NN, nstart + 86);
        const float*  xb = x + b * NN;
        const float2* yb = reinterpret_cast<const float2*>(y + b * NN * 2);
        #pragma unroll
        for (int rg = 0; rg < 4; ++rg) {
            const int row = rg * 32 + lane;
            const float tr = tmv[rg];
            float s0 = 0.f, s1 = 0.f, s2 = 0.f;
            for (int i = nstart; i < nend; ++i) {
                float  d  = tr - __ldg(xb + i);
                float2 yv = __ldg(yb + i);
                float d2 = d * d;
                float e0 = ex2f(C0 * d2);
                float e1 = ex2f(C1 * d2);
                float e2 = ex2f(C2 * d2);
                s0 += e0;
                s1 = fmaf(e1, yv.x, s1);
                s2 = fmaf(e2, yv.y, s2);
            }
            red[wrp][row] = make_float4(s0, s1, s2, 0.f);
        }
    }
    __syncthreads();

    // Combine 12 center/slice partials per row, normalize (128 threads)
    if (tid < MTB) {
        float d0 = 0.f, d1 = 0.f, d2 = 0.f;
        #pragma unroll
        for (int wdx = 0; wdx < NCTR; ++wdx) {
            float4 p = red[wdx][tid];
            d0 += p.x; d1 += p.y; d2 += p.z;
        }
        float inv = 1.f / (d0 + EPSV);
        zfin[tid] = make_float4(d0, d1 * inv, d2 * inv, 0.f);
    }
    __syncthreads();

    // Epilogue: 128 rows x 32 col-groups = 4096 float4 stores over 384 threads
    float4* out4 = reinterpret_cast<float4*>(out);
    const size_t rowbase = (size_t)(b * MM + m_base);
    for (int j = tid; j < MTB * 32; j += 384) {
        const int row = j >> 5;
        const int k4  = j & 31;
        const float4 z  = zfin[row];
        const float4 wa = sW[3 * k4];
        const float4 wb = sW[3 * k4 + 1];
        const float4 wc = sW[3 * k4 + 2];
        const float4 bb = sB[k4];
        float4 o;
        o.x = fmaf(z.x, wa.x, fmaf(z.y, wa.y, fmaf(z.z, wa.z, bb.x)));
        o.y = fmaf(z.x, wa.w, fmaf(z.y, wb.x, fmaf(z.z, wb.y, bb.y)));
        o.z = fmaf(z.x, wb.z, fmaf(z.y, wb.w, fmaf(z.z, wc.x, bb.z)));
        o.w = fmaf(z.x, wc.y, fmaf(z.y, wc.z, fmaf(z.z, wc.w, bb.w)));
        out4[(rowbase + row) * 32 + k4] = o;
    }
}

extern "C" void kernel_launch(void* const* d_in, const int* in_sizes, int n_in,
                              void* d_out, int out_size)
{
    const float* x     = (const float*)d_in[0];   // (8,1024,1)
    const float* y     = (const float*)d_in[1];   // (8,1024,2)
    const float* t     = (const float*)d_in[2];   // (8,2048,1)
    const float* sigma = (const float*)d_in[3];   // (3,)
    const float* W     = (const float*)d_in[4];   // (128,3)
    const float* bfc   = (const float*)d_in[5];   // (128,)
    float* out = (float*)d_out;                   // (8,2048,128)

    enc_one<<<NBLK, 384>>>(x, y, t, sigma, W, bfc, out);
}